// round 14
// baseline (speedup 1.0000x reference)
#include <cuda_runtime.h>

#define B_ROWS 4096
#define C_DIM  1024
#define K_POS  8
#define EPSF   1e-5f
#define NTHR   128               // 4 warps per block, ONE ROW PER WARP
#define WARPS  (NTHR / 32)
#define GRID   (B_ROWS / WARPS)
#define VPT    8                 // float4 iterations per lane (32 cols/lane)

#define LOG2E_F 1.4426950408889634f
#define LN2_F   0.6931471805599453f

// scratch for deterministic final reduction (no cudaMalloc allowed)
__device__ float        g_partials[B_ROWS];
__device__ unsigned int g_count;   // zero-init; last block resets -> replay safe

__device__ __forceinline__ float ex2f(float x){ float r; asm("ex2.approx.f32 %0,%1;" : "=f"(r) : "f"(x)); return r; }
__device__ __forceinline__ float lg2f(float x){ float r; asm("lg2.approx.f32 %0,%1;" : "=f"(r) : "f"(x)); return r; }
__device__ __forceinline__ float rcpf(float x){ float r; asm("rcp.approx.f32 %0,%1;" : "=f"(r) : "f"(x)); return r; }

__device__ __forceinline__ float warpSum(float v) {
#pragma unroll
    for (int o = 16; o > 0; o >>= 1) v += __shfl_xor_sync(0xffffffffu, v, o);
    return v;
}
// sum across lanes 0..7 (lanes >=8 hold 0), result valid in lanes 0..7
__device__ __forceinline__ float octSum(float v) {
#pragma unroll
    for (int o = 4; o > 0; o >>= 1) v += __shfl_xor_sync(0xffffffffu, v, o);
    return v;
}

__global__ __launch_bounds__(NTHR) void dudc_fused_kernel(
    const float* __restrict__ out1,
    const float* __restrict__ out2,
    const float* __restrict__ para_p,
    const int*   __restrict__ pos_idx,
    float*       __restrict__ out)
{
    const int tid  = threadIdx.x;
    const int wid  = tid >> 5;
    const int lane = tid & 31;
    const int row  = blockIdx.x * WARPS + wid;

    __shared__ float sred[WARPS];
    __shared__ unsigned int sh_ticket;

    const float*  r1  = out1 + (size_t)row * C_DIM;
    const float*  r2  = out2 + (size_t)row * C_DIM;
    const float4* r1v = reinterpret_cast<const float4*>(r1);
    const float4* r2v = reinterpret_cast<const float4*>(r2);

    // lanes 0..7 each own one positive label (inputs ~N(0,1): ex2 safe in f32)
    float y1p = 0.f, y2p = 0.f, e1p = 0.f, e2p = 0.f, i1p = 0.f, i2p = 0.f;
    if (lane < K_POS) {
        int pj = pos_idx[row * K_POS + lane];
        y1p = r1[pj] * LOG2E_F;
        y2p = r2[pj] * LOG2E_F;
        e1p = ex2f(y1p);   i1p = ex2f(-y1p);
        e2p = ex2f(y2p);   i2p = ex2f(-y2p);
    }

    // ---- SINGLE PASS: 7 MUFU/pair, 4 independent ex2 chains, NO arena ------
    // Taylor (A0-independent moments): sum e1*lg2(e2+A0)
    //   ~= p12 + log2e*(A0*M1 - A0^2/2*M2),   M1=sum e1/e2, M2=sum e1/e2^2
    // with 1/e computed as ex2(-y) (independent MUFU, no reciprocal chain).
    float s1 = 0.f, s2 = 0.f;          // sum e1, sum e2
    float p12 = 0.f, p21 = 0.f;        // sum e1*y2, sum e2*y1
    float M1 = 0.f, M2 = 0.f;          // sum e1*ib, sum e1*ib^2
    float N1 = 0.f, N2 = 0.f;          // sum e2*ia, sum e2*ia^2
    float q12 = 0.f, q21 = 0.f;        // sum sg1*lg2(1+ib), sum sg2*lg2(1+ia)
#pragma unroll
    for (int v = 0; v < VPT; v++) {
        float4 X1 = r1v[v * 32 + lane];
        float4 X2 = r2v[v * 32 + lane];
        float xs1[4] = {X1.x, X1.y, X1.z, X1.w};
        float xs2[4] = {X2.x, X2.y, X2.z, X2.w};
#pragma unroll
        for (int k = 0; k < 4; k++) {
            float y1 = xs1[k] * LOG2E_F;
            float y2 = xs2[k] * LOG2E_F;
            float ea = ex2f(y1);               // e^x1
            float ia = ex2f(-y1);              // e^-x1  (independent chain)
            float eb = ex2f(y2);               // e^x2
            float ib = ex2f(-y2);              // e^-x2
            s1 += ea;  s2 += eb;
            p12 = fmaf(ea, y2, p12);
            p21 = fmaf(eb, y1, p21);
            float w1 = ea * ib;                // e1/e2
            float w2 = eb * ia;                // e2/e1
            M1 += w1;  M2 = fmaf(w1, ib, M2);
            N1 += w2;  N2 = fmaf(w2, ia, N2);
            float u1 = 1.f + ia, u2 = 1.f + ib;
            float r  = rcpf(u1 * u2);          // ONE rcp for both sigmoids
            float sg1 = r * u2;                // sigmoid(x1) = 1/(1+e^-x1)
            float sg2 = r * u1;                // sigmoid(x2)
            // lg2(sigmoid(x2)) = -lg2(1+e^-x2)   (eps drop: rel err ~2e-5)
            q12 = fmaf(sg1, lg2f(u2), q12);    // = -m12 contribution
            q21 = fmaf(sg2, lg2f(u1), q21);
        }
    }

    const float S1   = warpSum(s1);
    const float S2   = warpSum(s2);
    const float P12  = warpSum(p12);
    const float P21  = warpSum(p21);
    const float M1t  = warpSum(M1);
    const float M2t  = warpSum(M2);
    const float N1t  = warpSum(N1);
    const float N2t  = warpSum(N2);
    const float Q12  = warpSum(q12);
    const float Q21  = warpSum(q21);

    // ------- remove positives from the moment sums (same Taylor form) -------
    float w1p = e1p * i2p;                 // e1p/e2p (0 on lanes >= 8)
    float w2p = e2p * i1p;
    float cS1  = octSum(e1p);
    float cS2  = octSum(e2p);
    float cP12 = octSum(e1p * y2p);
    float cP21 = octSum(e2p * y1p);
    float cM1  = octSum(w1p);
    float cM2  = octSum(w1p * i2p);
    float cN1  = octSum(w2p);
    float cN2  = octSum(w2p * i1p);

    float sj = 0.f;
    if (lane < K_POS) {
        const float S1n = S1 - cS1;
        const float S2n = S2 - cS2;
        const float A0  = EPSF * S2n;   // eps*Z2 Taylor point (j-dep dropped)
        const float B0  = EPSF * S1n;

        const float Un  = (P12 - cP12)
            + LOG2E_F * (A0 * (M1t - cM1) - 0.5f * A0 * A0 * (M2t - cM2));
        const float U2n = (P21 - cP21)
            + LOG2E_F * (B0 * (N1t - cN1) - 0.5f * B0 * B0 * (N2t - cN2));

        const float Z1 = S1n + e1p;
        const float Z2 = S2n + e2p;
        // log2-domain xent; ln2 folded in at the end. Positives exact.
        float x12 = lg2f(Z2) - (Un  + e1p * lg2f(e2p + EPSF * Z2)) * rcpf(Z1);
        float x21 = lg2f(Z1) - (U2n + e2p * lg2f(e1p + EPSF * Z1)) * rcpf(Z2);
        sj = x12 + x21;
    }
    sj = octSum(sj);

    if (lane == 0) {
        float para   = *para_p;
        float multi  = LN2_F * (Q12 + Q21);    // q accumulated -(sg*logsig)
        float single = LN2_F * sj * (1.0f / K_POS);
        g_partials[row] = para * multi + (1.0f - para) * single;
    }
    __syncthreads();                     // all rows of this block written

    if (tid == 0) {
        __threadfence();                 // publish partials before the ticket
        sh_ticket = atomicAdd(&g_count, 1u);
    }
    __syncthreads();

    // ------- last block performs the deterministic final sum ----------------
    if (sh_ticket == (unsigned)(gridDim.x - 1)) {
        __threadfence();                 // acquire: see all blocks' partials
        float v = 0.f;
#pragma unroll
        for (int i = tid; i < B_ROWS; i += NTHR) v += g_partials[i];
        v = warpSum(v);
        if (lane == 0) sred[wid] = v;
        __syncthreads();
        if (tid == 0) {
            float t = 0.f;
#pragma unroll
            for (int w = 0; w < WARPS; w++) t += sred[w];
            out[0] = t * (1.0f / (float)B_ROWS);
            g_count = 0;                 // reset for next graph replay
        }
    }
}

extern "C" void kernel_launch(void* const* d_in, const int* in_sizes, int n_in,
                              void* d_out, int out_size)
{
    const float* out1    = (const float*)d_in[0];
    const float* out2    = (const float*)d_in[1];
    const float* para    = (const float*)d_in[2];
    // d_in[3] = target (int32) -- unused, pos_idx fully determines the mask
    const int*   pos_idx = (const int*)d_in[4];
    float* out = (float*)d_out;

    dudc_fused_kernel<<<GRID, NTHR>>>(out1, out2, para, pos_idx, out);
}